// round 16
// baseline (speedup 1.0000x reference)
#include <cuda_runtime.h>
#include <math.h>
#include <stdint.h>

static constexpr int BB   = 64;
static constexpr int LL   = 128;
static constexpr int EMBD = 300;
static constexpr int HH   = 256;
static constexpr int NE   = 34;
static constexpr int NA   = 36;

// ---------------- scratch ----------------
__device__ float g_xT  [300 * 8192];              // [e][m=t*64+b]
__device__ float g_WT  [2 * 300 * 1024];          // [dir][k][row]
__device__ float g_xg  [LL * 2 * 4 * HH * BB];    // [t][dir][g][u][b]
__device__ float g_hsT [LL * 2 * HH * BB];        // [t][dir][u][b]
__device__ float g_evbase[LL * BB * NE];          // [t*64+b][34]
__device__ float g_base36[LL * BB * NA];          // [pos*64+b][36]
__device__ float g_thadd [LL * BB * NA];          // [t*64+b][36]
__device__ float g_Wcat [112 * 512];
__device__ float g_WeGT [33 * 34];
__device__ float g_WaGT [35 * 36];
__device__ unsigned char g_emask[BB * LL];
__device__ unsigned int g_barQ[512];              // 16 counters, 128B apart: [(dir*4+bslice)*2+half]*32

// ---------------- helpers ----------------
__device__ __forceinline__ uint64_t pk2(float x, float y) {
    uint64_t r; asm("mov.b64 %0,{%1,%2};" : "=l"(r) : "f"(x), "f"(y)); return r;
}
__device__ __forceinline__ uint64_t ffma2(uint64_t a, uint64_t b, uint64_t c) {
    uint64_t d; asm("fma.rn.f32x2 %0,%1,%2,%3;" : "=l"(d) : "l"(a), "l"(b), "l"(c)); return d;
}
__device__ __forceinline__ uint64_t addx2(uint64_t a, uint64_t b) {
    uint64_t d; asm("add.rn.f32x2 %0,%1,%2;" : "=l"(d) : "l"(a), "l"(b)); return d;
}
__device__ __forceinline__ float2 up2(uint64_t v) {
    float2 r; asm("mov.b64 {%0,%1},%2;" : "=f"(r.x), "=f"(r.y) : "l"(v)); return r;
}
__device__ __forceinline__ void wait_ctr(unsigned int* ctr, unsigned target) {
    unsigned v;
    while (1) {
        asm volatile("ld.acquire.gpu.global.u32 %0, [%1];" : "=r"(v) : "l"(ctr) : "memory");
        if (v >= target) break;
        __nanosleep(32);
    }
}

// ---------------- kernel 1a: gather | transW ----------------
__global__ void k_prep_a(const int* __restrict__ ids, const float* __restrict__ emb,
                         const float* __restrict__ Wf, const float* __restrict__ Wb) {
    __shared__ float ts[32][33];
    int bid = blockIdx.x;
    int tid = threadIdx.x;
    if (bid < 128) {
        int t = bid;
        int b = tid >> 2, q = tid & 3;
        int id = ids[b * LL + t];
        const float4* src = (const float4*)(emb + (size_t)id * EMBD);
#pragma unroll
        for (int j = 0; j < 19; j++) {
            int e4 = q + j * 4;
            if (e4 < 75) {
                float4 v = src[e4];
                int e = e4 * 4;
                size_t base = (size_t)e * 8192 + t * 64 + b;
                g_xT[base]          = v.x;
                g_xT[base + 8192]   = v.y;
                g_xT[base + 16384]  = v.z;
                g_xT[base + 24576]  = v.w;
            }
        }
    } else {
        int r3 = bid - 128;
        int z = r3 / 320;
        int rem = r3 % 320;
        int bxx = rem & 31;
        int byy = rem >> 5;
        const float* W = z ? Wb : Wf;
        float* out = g_WT + (size_t)z * 300 * 1024;
        int n0 = bxx * 32, k0 = byy * 32;
        int tx = tid & 31, ty = tid >> 5;
#pragma unroll
        for (int r = 0; r < 4; r++) {
            int row = ty + r * 8;
            int k = k0 + tx;
            if (k < 300) ts[row][tx] = W[(size_t)(n0 + row) * 300 + k];
        }
        __syncthreads();
#pragma unroll
        for (int r = 0; r < 4; r++) {
            int row = ty + r * 8;
            int k = k0 + row;
            if (k < 300) out[(size_t)k * 1024 + n0 + tx] = ts[tx][row];
        }
    }
}

// ---------------- kernel 1b: pack decode weights + reset counters ----------------
__global__ void k_prep_b(const float* __restrict__ We, const float* __restrict__ Wa) {
    int pb = blockIdx.x;
    int tid = threadIdx.x;
    if (pb == 0) {
        for (int i = tid; i < 512; i += 256) g_barQ[i] = 0u;
    }
    int gt = pb * 256 + tid;
    int stride = 64 * 256;
    for (int i = gt; i < 112 * 512; i += stride) {
        int n = i >> 9, k = i & 511;
        float v = 0.f;
        if (n < 34)       v = We[n * 545 + k];
        else if (n < 70)  v = Wa[(n - 34) * 1059 + k];
        else if (n < 106) v = Wa[(n - 70) * 1059 + 512 + k];
        g_Wcat[i] = v;
    }
    for (int i = gt; i < 33 * 34; i += stride) {
        int j = i / 34, e = i % 34;
        g_WeGT[i] = We[e * 545 + 512 + j];
    }
    for (int i = gt; i < 35 * 36; i += stride) {
        int j = i / 36, e = i % 36;
        g_WaGT[i] = Wa[e * 1059 + 1024 + j];
    }
}

// ---------------- kernel 2: input GEMM (R14 form, frozen) ----------------
__global__ void __launch_bounds__(512, 2)
k_gemm1(const float* __restrict__ bf, const float* __restrict__ bbv) {
    __shared__ float Xs[30 * 128];
    __shared__ float Ws[30 * 128];
    int nb = blockIdx.x;
    int mb = blockIdx.y;
    int dir = nb >> 3;
    int j0 = (nb & 7) * 128;
    int m0 = mb * 128;
    const float* WT = g_WT + (size_t)dir * 300 * 1024;
    const float* bias = dir ? bbv : bf;
    int tid = threadIdx.x;
    int lane = tid & 31, warp = tid >> 5;
    int tn = (warp & 3) * 4 + (lane >> 3);
    int tm = (warp >> 2) * 8 + (lane & 7);
    uint64_t acc[8][2];
#pragma unroll
    for (int i = 0; i < 8; i++) { acc[i][0] = 0ull; acc[i][1] = 0ull; }

    for (int kt = 0; kt < 10; kt++) {
        int k0 = kt * 30;
#pragma unroll
        for (int i = 0; i < 8; i++) {
            int idx = i * 512 + tid;
            if (idx < 3840) {
                int kk = idx >> 7, mm = idx & 127;
                Xs[idx] = g_xT[(size_t)(k0 + kk) * 8192 + m0 + mm];
                Ws[idx] = WT[(size_t)(k0 + kk) * 1024 + j0 + mm];
            }
        }
        __syncthreads();
#pragma unroll 5
        for (int kk = 0; kk < 30; kk++) {
            float4 w0 = *(const float4*)&Ws[kk * 128 + tn * 8];
            float4 w1 = *(const float4*)&Ws[kk * 128 + tn * 8 + 4];
            ulonglong2 x01 = *(const ulonglong2*)&Xs[kk * 128 + tm * 4];
            uint64_t wd[8];
            wd[0] = pk2(w0.x, w0.x); wd[1] = pk2(w0.y, w0.y);
            wd[2] = pk2(w0.z, w0.z); wd[3] = pk2(w0.w, w0.w);
            wd[4] = pk2(w1.x, w1.x); wd[5] = pk2(w1.y, w1.y);
            wd[6] = pk2(w1.z, w1.z); wd[7] = pk2(w1.w, w1.w);
#pragma unroll
            for (int wn = 0; wn < 8; wn++) {
                acc[wn][0] = ffma2(wd[wn], x01.x, acc[wn][0]);
                acc[wn][1] = ffma2(wd[wn], x01.y, acc[wn][1]);
            }
        }
        __syncthreads();
    }
    int m = m0 + tm * 4;
    int t = m >> 6;
    int bb = m & 63;
#pragma unroll
    for (int wn = 0; wn < 8; wn++) {
        int n = j0 + tn * 8 + wn;
        int g = n >> 8, u = n & 255;
        float bv = bias[n];
        uint64_t bd = pk2(bv, bv);
        ulonglong2 s0;
        s0.x = addx2(acc[wn][0], bd);
        s0.y = addx2(acc[wn][1], bd);
        *(ulonglong2*)&g_xg[(size_t)((t * 2 + dir) * 4 + g) * 16384 + u * 64 + bb] = s0;
    }
}

// ---------------- kernel 3: persistent LSTM, padded split-half counters ----------------
// R12 structure: 128 blocks, dir = bx>>6, r = bx&63, uslice = r&15 (u0 = uslice*16),
// bslice = r>>4. Thread = (uu = tid>>4, bl = tid&15).
// Counters 128B apart; half = uslice>>3 (8 producers each). Consumer pipelines:
// wait half0 -> refill k<128 -> MAC k<128 -> wait half1 -> refill -> MAC.
__global__ void __launch_bounds__(256, 1)
k_lstm_all(const float* __restrict__ Whf, const float* __restrict__ Whb) {
    extern __shared__ float sm[];
    uint64_t* wp = (uint64_t*)sm;            // 8192 u64 = 64 KB: [pair][uu][k]
    float* hsm = sm + 16384;                 // [bl][258]

    int bx = blockIdx.x;
    int dir = bx >> 6;
    int r = bx & 63;
    int uslice = r & 15;
    int u0 = uslice * 16;
    int bslice = r >> 4;
    int bg0 = bslice * 16;
    const float* W = dir ? Whb : Whf;
    int tid = threadIdx.x;
    int uu = tid >> 4, bl = tid & 15;
    int u = u0 + uu;
    int bglob = bg0 + bl;

#pragma unroll
    for (int i = 0; i < 32; i++) {
        int idx = i * 256 + tid;
        int pair = idx >> 12;
        int uq = (idx >> 8) & 15;
        int k = idx & 255;
        float a = W[(size_t)((pair * 2 + 0) * HH + u0 + uq) * HH + k];
        float b = W[(size_t)((pair * 2 + 1) * HH + u0 + uq) * HH + k];
        wp[idx] = pk2(a, b);
    }
    __syncthreads();

    float c = 0.f;
    int grp = dir * 4 + bslice;
    unsigned int* ctr0 = &g_barQ[(grp * 2 + 0) * 32];
    unsigned int* ctr1 = &g_barQ[(grp * 2 + 1) * 32];
    unsigned int* myc  = &g_barQ[(grp * 2 + (uslice >> 3)) * 32];
    const uint64_t* w0p = wp + uu * 256;
    const uint64_t* w1p = wp + 4096 + uu * 256;
    const float* hrow = hsm + bl * 258;

    for (int s = 0; s < LL; s++) {
        int t = dir ? (LL - 1 - s) : s;

        size_t xb = (size_t)(t * 2 + dir) * 4 * 16384 + (size_t)u * 64 + bglob;
        float vi = g_xg[xb];
        float vf = g_xg[xb + 16384];
        float vg = g_xg[xb + 2 * 16384];
        float vo = g_xg[xb + 3 * 16384];

        if (s > 0) {
            int tprev = dir ? (t + 1) : (t - 1);
            unsigned target = (unsigned)(s * 8);
            size_t hbase = (size_t)(tprev * 2 + dir) * 16384 + bg0;
            uint64_t a01 = 0ull, a23 = 0ull;

            // ---- half 0: units/k 0..127 ----
            if (tid == 0) wait_ctr(ctr0, target);
            __syncthreads();
#pragma unroll
            for (int i = 0; i < 8; i++) {
                int gi = i * 256 + tid;          // 0..2047
                int ku = gi >> 4;                // 0..127
                int bb = gi & 15;
                hsm[bb * 258 + ku] = g_hsT[hbase + (size_t)ku * 64 + bb];
            }
            __syncthreads();
#pragma unroll 8
            for (int k = 0; k < 128; k += 2) {
                ulonglong2 wA = *(const ulonglong2*)(w0p + k);
                ulonglong2 wB = *(const ulonglong2*)(w1p + k);
                float2 h2 = *(const float2*)(hrow + k);
                uint64_t hd0 = pk2(h2.x, h2.x);
                uint64_t hd1 = pk2(h2.y, h2.y);
                a01 = ffma2(wA.x, hd0, a01);
                a23 = ffma2(wB.x, hd0, a23);
                a01 = ffma2(wA.y, hd1, a01);
                a23 = ffma2(wB.y, hd1, a23);
            }

            // ---- half 1: units/k 128..255 ----
            if (tid == 0) wait_ctr(ctr1, target);
            __syncthreads();
#pragma unroll
            for (int i = 0; i < 8; i++) {
                int gi = i * 256 + tid;
                int ku = 128 + (gi >> 4);
                int bb = gi & 15;
                hsm[bb * 258 + ku] = g_hsT[hbase + (size_t)ku * 64 + bb];
            }
            __syncthreads();
#pragma unroll 8
            for (int k = 128; k < 256; k += 2) {
                ulonglong2 wA = *(const ulonglong2*)(w0p + k);
                ulonglong2 wB = *(const ulonglong2*)(w1p + k);
                float2 h2 = *(const float2*)(hrow + k);
                uint64_t hd0 = pk2(h2.x, h2.x);
                uint64_t hd1 = pk2(h2.y, h2.y);
                a01 = ffma2(wA.x, hd0, a01);
                a23 = ffma2(wB.x, hd0, a23);
                a01 = ffma2(wA.y, hd1, a01);
                a23 = ffma2(wB.y, hd1, a23);
            }
            float2 v01 = up2(a01);
            float2 v23 = up2(a23);
            vi += v01.x; vf += v01.y; vg += v23.x; vo += v23.y;
        }

        float si = 1.f / (1.f + expf(-vi));
        float sf = 1.f / (1.f + expf(-vf));
        float so = 1.f / (1.f + expf(-vo));
        c = sf * c + si * tanhf(vg);
        float h = so * tanhf(c);
        g_hsT[(size_t)(t * 2 + dir) * 16384 + (size_t)u * 64 + bglob] = h;

        if (s < LL - 1) {
            __syncthreads();
            if (tid == 0)
                asm volatile("red.release.gpu.global.add.u32 [%0], %1;" :: "l"(myc), "r"(1u) : "memory");
        }
    }
}

// ---------------- kernel 4: projection GEMM (R8 form) ----------------
__global__ void k_gemm2(const float* __restrict__ be, const float* __restrict__ ba) {
    __shared__ float Ash[16][64];
    __shared__ float Bsh[16][116];
    int t = blockIdx.x;
    const float* slabA = g_hsT + (size_t)t * 512 * 64;
    int tid = threadIdx.x;
    int tm = tid & 15, tn = tid >> 4;
    float acc[4][7] = {};
    for (int kt = 0; kt < 32; kt++) {
        int k0 = kt * 16;
        {
            int kk = tid >> 4, b4 = (tid & 15) * 4;
            *(float4*)&Ash[kk][b4] = *(const float4*)(slabA + (size_t)(k0 + kk) * 64 + b4);
        }
#pragma unroll
        for (int i = 0; i < 7; i++) {
            int idx = i * 256 + tid;
            int nn = idx >> 4, kk = idx & 15;
            Bsh[kk][nn] = g_Wcat[(size_t)nn * 512 + k0 + kk];
        }
        __syncthreads();
#pragma unroll
        for (int kk = 0; kk < 16; kk++) {
            float4 a = *(float4*)&Ash[kk][tm * 4];
#pragma unroll
            for (int j = 0; j < 7; j++) {
                float bv = Bsh[kk][tn * 7 + j];
                acc[0][j] += a.x * bv;
                acc[1][j] += a.y * bv;
                acc[2][j] += a.z * bv;
                acc[3][j] += a.w * bv;
            }
        }
        __syncthreads();
    }
#pragma unroll
    for (int i = 0; i < 4; i++) {
        int m = t * 64 + tm * 4 + i;
#pragma unroll
        for (int j = 0; j < 7; j++) {
            int n = tn * 7 + j;
            float v = acc[i][j];
            if (n < 34)       g_evbase[(size_t)m * NE + n]        = v + be[n];
            else if (n < 70)  g_base36[(size_t)m * NA + (n - 34)] = v + ba[n - 34];
            else if (n < 106) g_thadd [(size_t)m * NA + (n - 70)] = v;
        }
    }
}

// ---------------- kernel 5: event chains (prefetched) ----------------
__global__ void k_stageA(float* __restrict__ out_ev) {
    __shared__ float was[33 * 34];
    int tid = threadIdx.x;
    int b = tid >> 2, q = tid & 3;
    for (int i = tid; i < 33 * 34; i += 256) was[i] = g_WeGT[i];
    __syncthreads();
    int n0 = q * 9;
    int cnt = (q == 3) ? 7 : 9;
    float ctrg[9], cur[9];
#pragma unroll
    for (int i = 0; i < 9; i++) { ctrg[i] = 0.f; cur[i] = -1e30f; }
    {
        const float* eb = &g_evbase[(size_t)b * NE + n0];
#pragma unroll
        for (int i = 0; i < 9; i++) if (i < cnt) cur[i] = eb[i];
    }
    unsigned long long bits = 0ull;
    for (int t = 0; t < LL; t++) {
        float nxt[9];
        if (t < LL - 1) {
            const float* eb = &g_evbase[(size_t)((t + 1) * 64 + b) * NE + n0];
#pragma unroll
            for (int i = 0; i < 9; i++) if (i < cnt) nxt[i] = eb[i];
        }
        float o[9];
        float bestv = -1e30f;
        int besti = 1000;
#pragma unroll
        for (int i = 0; i < 9; i++) {
            if (i < cnt) {
                o[i] = cur[i] + ctrg[i];
                if (o[i] > bestv) { bestv = o[i]; besti = n0 + i; }
            }
        }
#pragma unroll
        for (int off = 1; off < 4; off <<= 1) {
            float ov = __shfl_xor_sync(0xffffffffu, bestv, off, 4);
            int   oi = __shfl_xor_sync(0xffffffffu, besti, off, 4);
            if (ov > bestv || (ov == bestv && oi < besti)) { bestv = ov; besti = oi; }
        }
        float* ob = &out_ev[((size_t)b * LL + t) * NE + n0];
#pragma unroll
        for (int i = 0; i < 9; i++) if (i < cnt) ob[i] = o[i];
        if (q == 0) g_emask[b * LL + t] = (besti > 0) ? 1 : 0;
        if (besti > 0) {
            int j = besti - 1;
            if (!((bits >> j) & 1ull)) {
                bits |= 1ull << j;
#pragma unroll
                for (int i = 0; i < 9; i++) if (i < cnt) ctrg[i] += was[j * NE + n0 + i];
            }
        }
#pragma unroll
        for (int i = 0; i < 9; i++) if (i < cnt) cur[i] = nxt[i];
    }
}

// ---------------- kernel 6: argument chains (double-buffered staging) ----------------
__global__ void k_stageB(float* __restrict__ out_arg) {
    __shared__ float was[35 * 36];
    __shared__ unsigned char em[LL];
    __shared__ float sbuf[2][64 * 36];
    int bx = blockIdx.x;
    int b = bx >> 1, ph = bx & 1;
    int tid = threadIdx.x;
    int p = tid >> 2;
    int pos = ph * 64 + p;
    int q = tid & 3;
    int n0 = q * 9;
    if (tid < LL) em[tid] = g_emask[b * LL + tid];
    for (int i = tid; i < 35 * 36; i += 256) was[i] = g_WaGT[i];
    __syncthreads();

    float base[9], C[9], thc[9];
    const float* bp = &g_base36[(size_t)(pos * 64 + b) * NA + n0];
#pragma unroll
    for (int i = 0; i < 9; i++) { base[i] = bp[i]; C[i] = 0.f; }
    {
        const float* th = &g_thadd[(size_t)b * NA + n0];
#pragma unroll
        for (int i = 0; i < 9; i++) thc[i] = th[i];
    }
    unsigned long long bits = 0ull;

    for (int t = 0; t < LL; t++) {
        float thn[9];
        if (t < LL - 1) {
            const float* th = &g_thadd[(size_t)((t + 1) * 64 + b) * NA + n0];
#pragma unroll
            for (int i = 0; i < 9; i++) thn[i] = th[i];
        }
        float o[9];
        float bestv = -1e30f;
        int besti = 1000;
#pragma unroll
        for (int i = 0; i < 9; i++) {
            o[i] = base[i] + C[i] + thc[i];
            if (o[i] > bestv) { bestv = o[i]; besti = n0 + i; }
        }
#pragma unroll
        for (int off = 1; off < 4; off <<= 1) {
            float ov = __shfl_xor_sync(0xffffffffu, bestv, off, 4);
            int   oi = __shfl_xor_sync(0xffffffffu, besti, off, 4);
            if (ov > bestv || (ov == bestv && oi < besti)) { bestv = ov; besti = oi; }
        }
        float* sb = &sbuf[t & 1][p * 36 + n0];
#pragma unroll
        for (int i = 0; i < 9; i++) sb[i] = o[i];
        if (em[t] && besti > 0) {
            int j = besti - 1;
            if (!((bits >> j) & 1ull)) {
                bits |= 1ull << j;
#pragma unroll
                for (int i = 0; i < 9; i++) C[i] += was[j * NA + n0 + i];
            }
        }
        __syncthreads();
        const float4* sb4 = (const float4*)sbuf[t & 1];
        float4* og = (float4*)(out_arg + ((size_t)(b * LL + t) * LL + ph * 64) * NA);
#pragma unroll
        for (int i2 = tid; i2 < 576; i2 += 256) og[i2] = sb4[i2];
#pragma unroll
        for (int i = 0; i < 9; i++) thc[i] = thn[i];
    }
}

// ---------------- launch ----------------
extern "C" void kernel_launch(void* const* d_in, const int* in_sizes, int n_in,
                              void* d_out, int out_size) {
    const int*   ids  = (const int*)  d_in[0];
    const float* emb  = (const float*)d_in[1];
    const float* Wihf = (const float*)d_in[2];
    const float* Whhf = (const float*)d_in[3];
    const float* bf   = (const float*)d_in[4];
    const float* Wihb = (const float*)d_in[5];
    const float* Whhb = (const float*)d_in[6];
    const float* bbv  = (const float*)d_in[7];
    const float* We   = (const float*)d_in[8];
    const float* be   = (const float*)d_in[9];
    const float* Wa   = (const float*)d_in[10];
    const float* ba   = (const float*)d_in[11];

    float* out_ev  = (float*)d_out;
    float* out_arg = out_ev + (size_t)BB * LL * NE;

    const int lstm_smem = 65536 + 16 * 258 * 4;   // 82048 B
    cudaFuncSetAttribute(k_lstm_all, cudaFuncAttributeMaxDynamicSharedMemorySize, lstm_smem);

    k_prep_a<<<768, 256>>>(ids, emb, Wihf, Wihb);
    k_prep_b<<<64, 256>>>(We, Wa);
    k_gemm1<<<dim3(16, 64), 512>>>(bf, bbv);
    k_lstm_all<<<128, 256, lstm_smem>>>(Whhf, Whhb);   // launch #4 -> profiled
    k_gemm2<<<128, 256>>>(be, ba);
    k_stageA<<<1, 256>>>(out_ev);
    k_stageB<<<128, 256>>>(out_arg);
}

// round 17
// speedup vs baseline: 1.1478x; 1.1478x over previous
#include <cuda_runtime.h>
#include <math.h>
#include <stdint.h>

static constexpr int BB   = 64;
static constexpr int LL   = 128;
static constexpr int EMBD = 300;
static constexpr int HH   = 256;
static constexpr int NE   = 34;
static constexpr int NA   = 36;

// ---------------- scratch ----------------
__device__ float g_xT  [300 * 8192];              // [e][m=t*64+b]
__device__ float g_WT  [2 * 300 * 1024];          // [dir][k][row]
__device__ float g_xg  [LL * 2 * 4 * HH * BB];    // [t][dir][g][u][b]
__device__ float g_hsT [LL * 2 * HH * BB];        // [t][dir][u][b]
__device__ float g_evbase[LL * BB * NE];          // [t*64+b][34]
__device__ float g_base36[LL * BB * NA];          // [pos*64+b][36]
__device__ float g_thadd [LL * BB * NA];          // [t*64+b][36]
__device__ float g_Wcat [112 * 512];
__device__ float g_WeGT [33 * 34];
__device__ float g_WaGT [35 * 36];
__device__ unsigned char g_emask[BB * LL];
__device__ unsigned int g_barQ[256];              // 8 counters, 128B apart: [dir*4+bslice]*32

// ---------------- helpers ----------------
__device__ __forceinline__ uint64_t pk2(float x, float y) {
    uint64_t r; asm("mov.b64 %0,{%1,%2};" : "=l"(r) : "f"(x), "f"(y)); return r;
}
__device__ __forceinline__ uint64_t ffma2(uint64_t a, uint64_t b, uint64_t c) {
    uint64_t d; asm("fma.rn.f32x2 %0,%1,%2,%3;" : "=l"(d) : "l"(a), "l"(b), "l"(c)); return d;
}
__device__ __forceinline__ uint64_t addx2(uint64_t a, uint64_t b) {
    uint64_t d; asm("add.rn.f32x2 %0,%1,%2;" : "=l"(d) : "l"(a), "l"(b)); return d;
}
__device__ __forceinline__ float2 up2(uint64_t v) {
    float2 r; asm("mov.b64 {%0,%1},%2;" : "=f"(r.x), "=f"(r.y) : "l"(v)); return r;
}

// ---------------- kernel 1 (fused): gather | transW | pack decode weights ----------------
__global__ void k_prep(const int* __restrict__ ids, const float* __restrict__ emb,
                       const float* __restrict__ Wf, const float* __restrict__ Wb,
                       const float* __restrict__ We, const float* __restrict__ Wa) {
    __shared__ float ts[32][33];
    int bid = blockIdx.x;
    int tid = threadIdx.x;
    if (bid < 128) {
        int t = bid;
        int b = tid >> 2, q = tid & 3;
        int id = ids[b * LL + t];
        const float4* src = (const float4*)(emb + (size_t)id * EMBD);
#pragma unroll
        for (int j = 0; j < 19; j++) {
            int e4 = q + j * 4;
            if (e4 < 75) {
                float4 v = src[e4];
                int e = e4 * 4;
                size_t base = (size_t)e * 8192 + t * 64 + b;
                g_xT[base]          = v.x;
                g_xT[base + 8192]   = v.y;
                g_xT[base + 16384]  = v.z;
                g_xT[base + 24576]  = v.w;
            }
        }
    } else if (bid < 768) {
        int r3 = bid - 128;
        int z = r3 / 320;
        int rem = r3 % 320;
        int bxx = rem & 31;
        int byy = rem >> 5;
        const float* W = z ? Wb : Wf;
        float* out = g_WT + (size_t)z * 300 * 1024;
        int n0 = bxx * 32, k0 = byy * 32;
        int tx = tid & 31, ty = tid >> 5;
#pragma unroll
        for (int r = 0; r < 4; r++) {
            int row = ty + r * 8;
            int k = k0 + tx;
            if (k < 300) ts[row][tx] = W[(size_t)(n0 + row) * 300 + k];
        }
        __syncthreads();
#pragma unroll
        for (int r = 0; r < 4; r++) {
            int row = ty + r * 8;
            int k = k0 + row;
            if (k < 300) out[(size_t)k * 1024 + n0 + tx] = ts[tx][row];
        }
    } else {
        int pb = bid - 768;
        if (pb == 0) {
            for (int i = tid; i < 256; i += 256) g_barQ[i] = 0u;
        }
        int gt = pb * 256 + tid;
        int stride = 64 * 256;
        for (int i = gt; i < 112 * 512; i += stride) {
            int n = i >> 9, k = i & 511;
            float v = 0.f;
            if (n < 34)       v = We[n * 545 + k];
            else if (n < 70)  v = Wa[(n - 34) * 1059 + k];
            else if (n < 106) v = Wa[(n - 70) * 1059 + 512 + k];
            g_Wcat[i] = v;
        }
        for (int i = gt; i < 33 * 34; i += stride) {
            int j = i / 34, e = i % 34;
            g_WeGT[i] = We[e * 545 + 512 + j];
        }
        for (int i = gt; i < 35 * 36; i += stride) {
            int j = i / 36, e = i % 36;
            g_WaGT[i] = Wa[e * 1059 + 1024 + j];
        }
    }
}

// ---------------- kernel 2: input GEMM (R14 form, frozen) ----------------
__global__ void __launch_bounds__(512, 2)
k_gemm1(const float* __restrict__ bf, const float* __restrict__ bbv) {
    __shared__ float Xs[30 * 128];
    __shared__ float Ws[30 * 128];
    int nb = blockIdx.x;
    int mb = blockIdx.y;
    int dir = nb >> 3;
    int j0 = (nb & 7) * 128;
    int m0 = mb * 128;
    const float* WT = g_WT + (size_t)dir * 300 * 1024;
    const float* bias = dir ? bbv : bf;
    int tid = threadIdx.x;
    int lane = tid & 31, warp = tid >> 5;
    int tn = (warp & 3) * 4 + (lane >> 3);
    int tm = (warp >> 2) * 8 + (lane & 7);
    uint64_t acc[8][2];
#pragma unroll
    for (int i = 0; i < 8; i++) { acc[i][0] = 0ull; acc[i][1] = 0ull; }

    for (int kt = 0; kt < 10; kt++) {
        int k0 = kt * 30;
#pragma unroll
        for (int i = 0; i < 8; i++) {
            int idx = i * 512 + tid;
            if (idx < 3840) {
                int kk = idx >> 7, mm = idx & 127;
                Xs[idx] = g_xT[(size_t)(k0 + kk) * 8192 + m0 + mm];
                Ws[idx] = WT[(size_t)(k0 + kk) * 1024 + j0 + mm];
            }
        }
        __syncthreads();
#pragma unroll 5
        for (int kk = 0; kk < 30; kk++) {
            float4 w0 = *(const float4*)&Ws[kk * 128 + tn * 8];
            float4 w1 = *(const float4*)&Ws[kk * 128 + tn * 8 + 4];
            ulonglong2 x01 = *(const ulonglong2*)&Xs[kk * 128 + tm * 4];
            uint64_t wd[8];
            wd[0] = pk2(w0.x, w0.x); wd[1] = pk2(w0.y, w0.y);
            wd[2] = pk2(w0.z, w0.z); wd[3] = pk2(w0.w, w0.w);
            wd[4] = pk2(w1.x, w1.x); wd[5] = pk2(w1.y, w1.y);
            wd[6] = pk2(w1.z, w1.z); wd[7] = pk2(w1.w, w1.w);
#pragma unroll
            for (int wn = 0; wn < 8; wn++) {
                acc[wn][0] = ffma2(wd[wn], x01.x, acc[wn][0]);
                acc[wn][1] = ffma2(wd[wn], x01.y, acc[wn][1]);
            }
        }
        __syncthreads();
    }
    int m = m0 + tm * 4;
    int t = m >> 6;
    int bb = m & 63;
#pragma unroll
    for (int wn = 0; wn < 8; wn++) {
        int n = j0 + tn * 8 + wn;
        int g = n >> 8, u = n & 255;
        float bv = bias[n];
        uint64_t bd = pk2(bv, bv);
        ulonglong2 s0;
        s0.x = addx2(acc[wn][0], bd);
        s0.y = addx2(acc[wn][1], bd);
        *(ulonglong2*)&g_xg[(size_t)((t * 2 + dir) * 4 + g) * 16384 + u * 64 + bb] = s0;
    }
}

// ---------------- kernel 3: persistent LSTM (R12 structure, padded counters) ----------------
__global__ void __launch_bounds__(256, 1)
k_lstm_all(const float* __restrict__ Whf, const float* __restrict__ Whb) {
    extern __shared__ float sm[];
    uint64_t* wp = (uint64_t*)sm;            // 8192 u64 = 64 KB: [pair][uu][k]
    float* hsm = sm + 16384;                 // [bl][258]

    int bx = blockIdx.x;
    int dir = bx >> 6;
    int r = bx & 63;
    int u0 = (r & 15) * 16;
    int bg0 = (r >> 4) * 16;
    const float* W = dir ? Whb : Whf;
    int tid = threadIdx.x;
    int uu = tid >> 4, bl = tid & 15;
    int u = u0 + uu;
    int bglob = bg0 + bl;

#pragma unroll
    for (int i = 0; i < 32; i++) {
        int idx = i * 256 + tid;
        int pair = idx >> 12;
        int uq = (idx >> 8) & 15;
        int k = idx & 255;
        float a = W[(size_t)((pair * 2 + 0) * HH + u0 + uq) * HH + k];
        float b = W[(size_t)((pair * 2 + 1) * HH + u0 + uq) * HH + k];
        wp[idx] = pk2(a, b);
    }
    __syncthreads();

    float c = 0.f;
    unsigned int* ctr = &g_barQ[(dir * 4 + (r >> 4)) * 32];   // 128B apart
    const uint64_t* w0p = wp + uu * 256;
    const uint64_t* w1p = wp + 4096 + uu * 256;
    const float* hrow = hsm + bl * 258;

    for (int s = 0; s < LL; s++) {
        int t = dir ? (LL - 1 - s) : s;

        size_t xb = (size_t)(t * 2 + dir) * 4 * 16384 + (size_t)u * 64 + bglob;
        float vi = g_xg[xb];
        float vf = g_xg[xb + 16384];
        float vg = g_xg[xb + 2 * 16384];
        float vo = g_xg[xb + 3 * 16384];

        if (s > 0) {
            int tprev = dir ? (t + 1) : (t - 1);
            if (tid == 0) {
                unsigned target = (unsigned)(s * 16);
                unsigned v;
                while (1) {
                    asm volatile("ld.acquire.gpu.global.u32 %0, [%1];" : "=r"(v) : "l"(ctr) : "memory");
                    if (v >= target) break;
                    __nanosleep(32);
                }
            }
            __syncthreads();
            size_t hbase = (size_t)(tprev * 2 + dir) * 16384 + bg0;
#pragma unroll
            for (int i = 0; i < 16; i++) {
                int gi = i * 256 + tid;
                int ku = gi >> 4;
                int bb = gi & 15;
                hsm[bb * 258 + ku] = g_hsT[hbase + (size_t)ku * 64 + bb];
            }
            __syncthreads();

            uint64_t a01 = 0ull, a23 = 0ull;
#pragma unroll 8
            for (int k = 0; k < HH; k += 2) {
                ulonglong2 wA = *(const ulonglong2*)(w0p + k);
                ulonglong2 wB = *(const ulonglong2*)(w1p + k);
                float2 h2 = *(const float2*)(hrow + k);
                uint64_t hd0 = pk2(h2.x, h2.x);
                uint64_t hd1 = pk2(h2.y, h2.y);
                a01 = ffma2(wA.x, hd0, a01);
                a23 = ffma2(wB.x, hd0, a23);
                a01 = ffma2(wA.y, hd1, a01);
                a23 = ffma2(wB.y, hd1, a23);
            }
            float2 v01 = up2(a01);
            float2 v23 = up2(a23);
            vi += v01.x; vf += v01.y; vg += v23.x; vo += v23.y;
        }

        float si = 1.f / (1.f + expf(-vi));
        float sf = 1.f / (1.f + expf(-vf));
        float so = 1.f / (1.f + expf(-vo));
        c = sf * c + si * tanhf(vg);
        float h = so * tanhf(c);
        g_hsT[(size_t)(t * 2 + dir) * 16384 + (size_t)u * 64 + bglob] = h;

        if (s < LL - 1) {
            __syncthreads();
            if (tid == 0)
                asm volatile("red.release.gpu.global.add.u32 [%0], %1;" :: "l"(ctr), "r"(1u) : "memory");
        }
    }
}

// ---------------- kernel 4: projection GEMM, 256 blocks x 128 threads ----------------
// bx: t = bx>>1, mh = (bx&1)*32 -> 32 m-rows per block.
__global__ void k_gemm2(const float* __restrict__ be, const float* __restrict__ ba) {
    __shared__ float Ash[16][32];
    __shared__ float Bsh[16][116];
    int bx = blockIdx.x;
    int t = bx >> 1;
    int mh = (bx & 1) * 32;
    const float* slabA = g_hsT + (size_t)t * 512 * 64;
    int tid = threadIdx.x;     // 128
    int tm = tid & 7, tn = tid >> 3;   // tm: 8 tiles x 4 rows; tn: 16 tiles x 7 n
    float acc[4][7] = {};
    for (int kt = 0; kt < 32; kt++) {
        int k0 = kt * 16;
        {
            int kk = tid >> 3, b4 = (tid & 7) * 4;   // 16 x 8 x 4 = 512
            *(float4*)&Ash[kk][b4] = *(const float4*)(slabA + (size_t)(k0 + kk) * 64 + mh + b4);
        }
#pragma unroll
        for (int i = 0; i < 14; i++) {
            int idx = i * 128 + tid;                 // 1792 = 112 x 16
            int nn = idx >> 4, kk = idx & 15;
            Bsh[kk][nn] = g_Wcat[(size_t)nn * 512 + k0 + kk];
        }
        __syncthreads();
#pragma unroll
        for (int kk = 0; kk < 16; kk++) {
            float4 a = *(float4*)&Ash[kk][tm * 4];
#pragma unroll
            for (int j = 0; j < 7; j++) {
                float bv = Bsh[kk][tn * 7 + j];
                acc[0][j] += a.x * bv;
                acc[1][j] += a.y * bv;
                acc[2][j] += a.z * bv;
                acc[3][j] += a.w * bv;
            }
        }
        __syncthreads();
    }
#pragma unroll
    for (int i = 0; i < 4; i++) {
        int m = t * 64 + mh + tm * 4 + i;
#pragma unroll
        for (int j = 0; j < 7; j++) {
            int n = tn * 7 + j;
            float v = acc[i][j];
            if (n < 34)       g_evbase[(size_t)m * NE + n]        = v + be[n];
            else if (n < 70)  g_base36[(size_t)m * NA + (n - 34)] = v + ba[n - 34];
            else if (n < 106) g_thadd [(size_t)m * NA + (n - 70)] = v;
        }
    }
}

// ---------------- kernel 5: event chains, 8 blocks x 32 threads ----------------
__global__ void k_stageA(float* __restrict__ out_ev) {
    __shared__ float was[33 * 34];
    int tid = threadIdx.x;     // 32
    int b = blockIdx.x * 8 + (tid >> 2);
    int q = tid & 3;
    for (int i = tid; i < 33 * 34; i += 32) was[i] = g_WeGT[i];
    __syncthreads();
    int n0 = q * 9;
    int cnt = (q == 3) ? 7 : 9;
    float ctrg[9], cur[9];
#pragma unroll
    for (int i = 0; i < 9; i++) { ctrg[i] = 0.f; cur[i] = -1e30f; }
    {
        const float* eb = &g_evbase[(size_t)b * NE + n0];
#pragma unroll
        for (int i = 0; i < 9; i++) if (i < cnt) cur[i] = eb[i];
    }
    unsigned long long bits = 0ull;
    for (int t = 0; t < LL; t++) {
        float nxt[9];
        if (t < LL - 1) {
            const float* eb = &g_evbase[(size_t)((t + 1) * 64 + b) * NE + n0];
#pragma unroll
            for (int i = 0; i < 9; i++) if (i < cnt) nxt[i] = eb[i];
        }
        float o[9];
        float bestv = -1e30f;
        int besti = 1000;
#pragma unroll
        for (int i = 0; i < 9; i++) {
            if (i < cnt) {
                o[i] = cur[i] + ctrg[i];
                if (o[i] > bestv) { bestv = o[i]; besti = n0 + i; }
            }
        }
#pragma unroll
        for (int off = 1; off < 4; off <<= 1) {
            float ov = __shfl_xor_sync(0xffffffffu, bestv, off, 4);
            int   oi = __shfl_xor_sync(0xffffffffu, besti, off, 4);
            if (ov > bestv || (ov == bestv && oi < besti)) { bestv = ov; besti = oi; }
        }
        float* ob = &out_ev[((size_t)b * LL + t) * NE + n0];
#pragma unroll
        for (int i = 0; i < 9; i++) if (i < cnt) ob[i] = o[i];
        if (q == 0) g_emask[b * LL + t] = (besti > 0) ? 1 : 0;
        if (besti > 0) {
            int j = besti - 1;
            if (!((bits >> j) & 1ull)) {
                bits |= 1ull << j;
#pragma unroll
                for (int i = 0; i < 9; i++) if (i < cnt) ctrg[i] += was[j * NE + n0 + i];
            }
        }
#pragma unroll
        for (int i = 0; i < 9; i++) if (i < cnt) cur[i] = nxt[i];
    }
}

// ---------------- kernel 6: argument chains (double-buffered staging) ----------------
__global__ void k_stageB(float* __restrict__ out_arg) {
    __shared__ float was[35 * 36];
    __shared__ unsigned char em[LL];
    __shared__ float sbuf[2][64 * 36];
    int bx = blockIdx.x;
    int b = bx >> 1, ph = bx & 1;
    int tid = threadIdx.x;
    int p = tid >> 2;
    int pos = ph * 64 + p;
    int q = tid & 3;
    int n0 = q * 9;
    if (tid < LL) em[tid] = g_emask[b * LL + tid];
    for (int i = tid; i < 35 * 36; i += 256) was[i] = g_WaGT[i];
    __syncthreads();

    float base[9], C[9], thc[9];
    const float* bp = &g_base36[(size_t)(pos * 64 + b) * NA + n0];
#pragma unroll
    for (int i = 0; i < 9; i++) { base[i] = bp[i]; C[i] = 0.f; }
    {
        const float* th = &g_thadd[(size_t)b * NA + n0];
#pragma unroll
        for (int i = 0; i < 9; i++) thc[i] = th[i];
    }
    unsigned long long bits = 0ull;

    for (int t = 0; t < LL; t++) {
        float thn[9];
        if (t < LL - 1) {
            const float* th = &g_thadd[(size_t)((t + 1) * 64 + b) * NA + n0];
#pragma unroll
            for (int i = 0; i < 9; i++) thn[i] = th[i];
        }
        float o[9];
        float bestv = -1e30f;
        int besti = 1000;
#pragma unroll
        for (int i = 0; i < 9; i++) {
            o[i] = base[i] + C[i] + thc[i];
            if (o[i] > bestv) { bestv = o[i]; besti = n0 + i; }
        }
#pragma unroll
        for (int off = 1; off < 4; off <<= 1) {
            float ov = __shfl_xor_sync(0xffffffffu, bestv, off, 4);
            int   oi = __shfl_xor_sync(0xffffffffu, besti, off, 4);
            if (ov > bestv || (ov == bestv && oi < besti)) { bestv = ov; besti = oi; }
        }
        float* sb = &sbuf[t & 1][p * 36 + n0];
#pragma unroll
        for (int i = 0; i < 9; i++) sb[i] = o[i];
        if (em[t] && besti > 0) {
            int j = besti - 1;
            if (!((bits >> j) & 1ull)) {
                bits |= 1ull << j;
#pragma unroll
                for (int i = 0; i < 9; i++) C[i] += was[j * NA + n0 + i];
            }
        }
        __syncthreads();
        const float4* sb4 = (const float4*)sbuf[t & 1];
        float4* og = (float4*)(out_arg + ((size_t)(b * LL + t) * LL + ph * 64) * NA);
#pragma unroll
        for (int i2 = tid; i2 < 576; i2 += 256) og[i2] = sb4[i2];
#pragma unroll
        for (int i = 0; i < 9; i++) thc[i] = thn[i];
    }
}

// ---------------- launch ----------------
extern "C" void kernel_launch(void* const* d_in, const int* in_sizes, int n_in,
                              void* d_out, int out_size) {
    const int*   ids  = (const int*)  d_in[0];
    const float* emb  = (const float*)d_in[1];
    const float* Wihf = (const float*)d_in[2];
    const float* Whhf = (const float*)d_in[3];
    const float* bf   = (const float*)d_in[4];
    const float* Wihb = (const float*)d_in[5];
    const float* Whhb = (const float*)d_in[6];
    const float* bbv  = (const float*)d_in[7];
    const float* We   = (const float*)d_in[8];
    const float* be   = (const float*)d_in[9];
    const float* Wa   = (const float*)d_in[10];
    const float* ba   = (const float*)d_in[11];

    float* out_ev  = (float*)d_out;
    float* out_arg = out_ev + (size_t)BB * LL * NE;

    const int lstm_smem = 65536 + 16 * 258 * 4;   // 82048 B
    cudaFuncSetAttribute(k_lstm_all, cudaFuncAttributeMaxDynamicSharedMemorySize, lstm_smem);

    k_prep<<<832, 256>>>(ids, emb, Wihf, Wihb, We, Wa);
    k_gemm1<<<dim3(16, 64), 512>>>(bf, bbv);
    k_lstm_all<<<128, 256, lstm_smem>>>(Whhf, Whhb);
    k_gemm2<<<256, 128>>>(be, ba);
    k_stageA<<<8, 32>>>(out_ev);
    k_stageB<<<128, 256>>>(out_arg);
}